// round 9
// baseline (speedup 1.0000x reference)
#include <cuda_runtime.h>
#include <cuda_fp16.h>
#include <math.h>

#define C   128
#define HW  1024
#define N   4096
#define K   128
#define INV_TEMP (1.0f/0.07f)

// Scratch: normalized row-major [N, C] fp16 features (1 MB each).
__device__ __align__(16) __half g_qh[N * C];
__device__ __align__(16) __half g_kh[N * C];

// One block per (tensor p, batch b, 32-wide hw chunk): 2*4*32 = 256 blocks.
__global__ void normalize_kernel(const float* __restrict__ fq,
                                 const float* __restrict__ fk,
                                 float* __restrict__ out) {
    __shared__ float s[C][33];
    __shared__ float ps[8][32];
    __shared__ float inv[32];

    if (blockIdx.x == 0 && threadIdx.x == 0) out[0] = 0.0f;

    const int p   = blockIdx.x >> 7;          // 0 = q, 1 = k
    const int b   = (blockIdx.x >> 5) & 3;
    const int hw0 = (blockIdx.x & 31) << 5;
    const int t   = threadIdx.x;

    const float* src = (p == 0 ? fq : fk) + (size_t)b * C * HW + hw0;

    #pragma unroll
    for (int iter = 0; iter < 16; iter++) {
        int e = t + iter * 256;
        int c = e >> 5, i = e & 31;
        s[c][i] = src[c * HW + i];
    }
    __syncthreads();

    {
        int i = t & 31, c0 = t >> 5;
        float acc = 0.0f;
        #pragma unroll
        for (int c = c0; c < C; c += 8) { float v = s[c][i]; acc += v * v; }
        ps[c0][i] = acc;
    }
    __syncthreads();
    if (t < 32) {
        float sum = 0.0f;
        #pragma unroll
        for (int r = 0; r < 8; r++) sum += ps[r][t];
        inv[t] = 1.0f / fmaxf(sqrtf(sum), 1e-12f);
    }
    __syncthreads();

    __half* dst = (p == 0 ? g_qh : g_kh) + ((size_t)b * HW + hw0) * C;
    #pragma unroll
    for (int iter = 0; iter < 16; iter++) {
        int e  = t + iter * 256;
        int ii = e >> 7, c = e & 127;
        dst[ii * C + c] = __float2half(s[c][ii] * inv[ii]);
    }
}

// Lane-local 16-element partial dot: one HFMA2 chain over 8 half2, one convert.
__device__ __forceinline__ float dot16h(const uint4& qv0, const uint4& qv1,
                                        const uint4& kv0, const uint4& kv1) {
    const __half2* q = reinterpret_cast<const __half2*>(&qv0);
    const __half2* Q = reinterpret_cast<const __half2*>(&qv1);
    const __half2* k = reinterpret_cast<const __half2*>(&kv0);
    const __half2* Kk = reinterpret_cast<const __half2*>(&kv1);
    __half2 acc = __hmul2(q[0], k[0]);
    acc = __hfma2(q[1], k[1], acc);
    acc = __hfma2(q[2], k[2], acc);
    acc = __hfma2(q[3], k[3], acc);
    acc = __hfma2(Q[0], Kk[0], acc);
    acc = __hfma2(Q[1], Kk[1], acc);
    acc = __hfma2(Q[2], Kk[2], acc);
    acc = __hfma2(Q[3], Kk[3], acc);
    const float2 f = __half22float2(acc);
    return f.x + f.y;
}

// 8-lane-group all-reduce on a fully converged warp: xor 4/2/1 stay inside
// the 8-lane group; EVERY lane of the group ends with the group sum.
__device__ __forceinline__ float group8_allsum(float p) {
    p += __shfl_xor_sync(0xffffffffu, p, 4);
    p += __shfl_xor_sync(0xffffffffu, p, 2);
    p += __shfl_xor_sync(0xffffffffu, p, 1);
    return p;
}

// Warp-per-row: grid 512 x 8 warps = 4096 rows. No __syncthreads, no shared
// logits, no serial tail. Each warp: 4 groups of 8 lanes; group g computes
// dots for slots T*8+g and T*8+g+4 over 17 uniform trips (slots 129..135 are
// dummies, discarded by predicate). Online sum of exp (no max needed:
// |logit| <= 1/0.07, exp sum < 2e8, exact in fp32). All shfls full-mask on
// uniform control flow.
__global__ void pnce_kernel(const int* __restrict__ negi,
                            float* __restrict__ out) {
    __shared__ int sneg[8][K];

    const int t    = threadIdx.x;
    const int w    = t >> 5;
    const int lane = t & 31;
    const int g    = lane >> 3;     // group 0..3
    const int l8   = lane & 7;      // lane within group
    const int n    = (blockIdx.x << 3) + w;

    // Stage this warp's 128 indices (coalesced), warp-local visibility only.
    #pragma unroll
    for (int i = lane; i < K; i += 32) sneg[w][i] = negi[n * K + i];
    __syncwarp();

    // Query: lane's 16 channels (L1-broadcast across lanes/groups).
    const uint4* qptr = reinterpret_cast<const uint4*>(g_qh + (size_t)n * C);
    const uint4 qv0 = qptr[l8];
    const uint4 qv1 = qptr[l8 + 8];

    float s    = 0.0f;   // running sum of exp(logit) (identical within group)
    float lpos = 0.0f;   // positive logit (set by group 0, trip 0)

    #pragma unroll 1
    for (int T = 0; T < 17; T++) {
        const int j1 = T * 8 + g;
        const int j2 = j1 + 4;

        const int idx1 = (j1 == 0) ? n : ((j1 <= 128) ? sneg[w][j1 - 1] : n);
        const int idx2 = (j2 <= 128) ? sneg[w][j2 - 1] : n;

        const uint4* ka = reinterpret_cast<const uint4*>(g_kh + (size_t)idx1 * C);
        const uint4* kb = reinterpret_cast<const uint4*>(g_kh + (size_t)idx2 * C);
        const uint4 ka0 = ka[l8];
        const uint4 ka1 = ka[l8 + 8];
        const uint4 kb0 = kb[l8];
        const uint4 kb1 = kb[l8 + 8];

        float d1 = group8_allsum(dot16h(qv0, qv1, ka0, ka1));
        float d2 = group8_allsum(dot16h(qv0, qv1, kb0, kb1));

        const float l1 = d1 * INV_TEMP;
        const float l2 = d2 * INV_TEMP;
        if (j1 <= 128) s += __expf(l1);
        if (j2 <= 128) s += __expf(l2);
        if (j1 == 0) lpos = l1;       // only group 0, trip 0
    }

    // Cross-group combine: lanes within a group hold identical s, so xor
    // shfl at 8 then 16 sums each group exactly once into every lane.
    s += __shfl_xor_sync(0xffffffffu, s, 8);
    s += __shfl_xor_sync(0xffffffffu, s, 16);

    if (lane == 0) {
        const float lse = logf(s);
        atomicAdd(out, (lse - lpos) * (1.0f / (float)N));
    }
}

extern "C" void kernel_launch(void* const* d_in, const int* in_sizes, int n_in,
                              void* d_out, int out_size) {
    const float* feat_q = (const float*)d_in[0];
    const float* feat_k = (const float*)d_in[1];
    const int*   negi   = (const int*)d_in[2];
    float*       out    = (float*)d_out;

    normalize_kernel<<<256, 256>>>(feat_q, feat_k, out);
    pnce_kernel<<<N / 8, 256>>>(negi, out);
}

// round 10
// speedup vs baseline: 1.0241x; 1.0241x over previous
#include <cuda_runtime.h>
#include <cuda_fp16.h>
#include <math.h>

#define C   128
#define HW  1024
#define N   4096
#define K   128
#define INV_TEMP (1.0f/0.07f)

// Scratch: normalized row-major [N, C] fp16 features (1 MB each).
__device__ __align__(16) __half g_qh[N * C];
__device__ __align__(16) __half g_kh[N * C];

// One block per (tensor p, batch b, 32-wide hw chunk): 2*4*32 = 256 blocks.
__global__ void normalize_kernel(const float* __restrict__ fq,
                                 const float* __restrict__ fk,
                                 float* __restrict__ out) {
    __shared__ float s[C][33];
    __shared__ float ps[8][32];
    __shared__ float inv[32];

    if (blockIdx.x == 0 && threadIdx.x == 0) out[0] = 0.0f;

    const int p   = blockIdx.x >> 7;          // 0 = q, 1 = k
    const int b   = (blockIdx.x >> 5) & 3;
    const int hw0 = (blockIdx.x & 31) << 5;
    const int t   = threadIdx.x;

    const float* src = (p == 0 ? fq : fk) + (size_t)b * C * HW + hw0;

    #pragma unroll
    for (int iter = 0; iter < 16; iter++) {
        int e = t + iter * 256;
        int c = e >> 5, i = e & 31;
        s[c][i] = src[c * HW + i];
    }
    __syncthreads();

    {
        int i = t & 31, c0 = t >> 5;
        float acc = 0.0f;
        #pragma unroll
        for (int c = c0; c < C; c += 8) { float v = s[c][i]; acc += v * v; }
        ps[c0][i] = acc;
    }
    __syncthreads();
    if (t < 32) {
        float sum = 0.0f;
        #pragma unroll
        for (int r = 0; r < 8; r++) sum += ps[r][t];
        inv[t] = 1.0f / fmaxf(sqrtf(sum), 1e-12f);
    }
    __syncthreads();

    __half* dst = (p == 0 ? g_qh : g_kh) + ((size_t)b * HW + hw0) * C;
    #pragma unroll
    for (int iter = 0; iter < 16; iter++) {
        int e  = t + iter * 256;
        int ii = e >> 7, c = e & 127;
        dst[ii * C + c] = __float2half(s[c][ii] * inv[ii]);
    }
}

// Lane-local 16-element partial dot: one HFMA2 chain over 8 half2, one convert.
__device__ __forceinline__ float dot16h(const uint4& qv0, const uint4& qv1,
                                        const uint4& kv0, const uint4& kv1) {
    const __half2* q = reinterpret_cast<const __half2*>(&qv0);
    const __half2* Q = reinterpret_cast<const __half2*>(&qv1);
    const __half2* k = reinterpret_cast<const __half2*>(&kv0);
    const __half2* Kk = reinterpret_cast<const __half2*>(&kv1);
    __half2 acc = __hmul2(q[0], k[0]);
    acc = __hfma2(q[1], k[1], acc);
    acc = __hfma2(q[2], k[2], acc);
    acc = __hfma2(q[3], k[3], acc);
    acc = __hfma2(Q[0], Kk[0], acc);
    acc = __hfma2(Q[1], Kk[1], acc);
    acc = __hfma2(Q[2], Kk[2], acc);
    acc = __hfma2(Q[3], Kk[3], acc);
    const float2 f = __half22float2(acc);
    return f.x + f.y;
}

// 8-lane-group all-reduce on a fully converged warp: xor 4/2/1 stay inside
// the 8-lane group; EVERY lane of the group ends with the group sum.
__device__ __forceinline__ float group8_allsum(float p) {
    p += __shfl_xor_sync(0xffffffffu, p, 4);
    p += __shfl_xor_sync(0xffffffffu, p, 2);
    p += __shfl_xor_sync(0xffffffffu, p, 1);
    return p;
}

// Two warps per row (grid 1024 x 8 warps = 8192 warps -> ~86% occ).
// Half 0: slots 0..64 (9 trips, dummies idx=n). Half 1: slots 65..128
// (8 trips, none). Online exp-sum (|logit| <= 1/0.07 -> fp32-exact, no max
// pass). Valid shared reads stay within the half each warp itself staged, so
// __syncwarp suffices; the single __syncthreads covers the spart combine.
__global__ void pnce_kernel(const int* __restrict__ negi,
                            float* __restrict__ out) {
    __shared__ int   sneg[4][K];
    __shared__ float spart[4][2];

    const int t    = threadIdx.x;
    const int w    = t >> 5;
    const int lane = t & 31;
    const int pr   = w >> 1;        // row slot in block 0..3
    const int h    = w & 1;         // half 0/1
    const int g    = lane >> 3;     // group 0..3
    const int l8   = lane & 7;      // lane within group
    const int n    = (blockIdx.x << 2) + pr;

    // Warp h stages indices [h*64, h*64+64) of its row (coalesced).
    {
        const int i0 = h * 64 + lane;
        sneg[pr][i0]      = negi[n * K + i0];
        sneg[pr][i0 + 32] = negi[n * K + i0 + 32];
    }
    __syncwarp();

    const uint4* qptr = reinterpret_cast<const uint4*>(g_qh + (size_t)n * C);
    const uint4 qv0 = qptr[l8];
    const uint4 qv1 = qptr[l8 + 8];

    float s    = 0.0f;
    float lpos = 0.0f;              // set by half 0, group 0, trip 0

    const int base  = h ? 65 : 0;
    const int trips = h ? 8 : 9;

    for (int T = 0; T < trips; T++) {
        const int j1 = base + T * 8 + g;
        const int j2 = j1 + 4;
        const bool v1 = h ? true : (j1 <= 64);
        const bool v2 = h ? true : (j2 <= 64);

        const int idx1 = (j1 == 0) ? n : (v1 ? sneg[pr][j1 - 1] : n);
        const int idx2 = v2 ? sneg[pr][j2 - 1] : n;

        const uint4* ka = reinterpret_cast<const uint4*>(g_kh + (size_t)idx1 * C);
        const uint4* kb = reinterpret_cast<const uint4*>(g_kh + (size_t)idx2 * C);
        const uint4 ka0 = ka[l8];
        const uint4 ka1 = ka[l8 + 8];
        const uint4 kb0 = kb[l8];
        const uint4 kb1 = kb[l8 + 8];

        float d1 = group8_allsum(dot16h(qv0, qv1, ka0, ka1));
        float d2 = group8_allsum(dot16h(qv0, qv1, kb0, kb1));

        const float l1 = d1 * INV_TEMP;
        const float l2 = d2 * INV_TEMP;
        if (v1) s += __expf(l1);
        if (v2) s += __expf(l2);
        if (j1 == 0) lpos = l1;
    }

    // Cross-group combine within the warp (groups hold identical sums).
    s += __shfl_xor_sync(0xffffffffu, s, 8);
    s += __shfl_xor_sync(0xffffffffu, s, 16);
    if (lane == 0) spart[pr][h] = s;
    __syncthreads();

    if (h == 0 && lane == 0) {
        const float total = spart[pr][0] + spart[pr][1];
        atomicAdd(out, (__logf(total) - lpos) * (1.0f / (float)N));
    }
}

extern "C" void kernel_launch(void* const* d_in, const int* in_sizes, int n_in,
                              void* d_out, int out_size) {
    const float* feat_q = (const float*)d_in[0];
    const float* feat_k = (const float*)d_in[1];
    const int*   negi   = (const int*)d_in[2];
    float*       out    = (float*)d_out;

    normalize_kernel<<<256, 256>>>(feat_q, feat_k, out);
    pnce_kernel<<<N / 4, 256>>>(negi, out);
}